// round 1
// baseline (speedup 1.0000x reference)
#include <cuda_runtime.h>
#include <math.h>

#define D_MODEL 256
#define NH 8
#define NL 4
#define NP 4
#define HD 32
#define BATCH 2
#define S_TOT 13294
#define LQ 13294
#define M_ROWS (BATCH * LQ)   // 26588
#define NATTN (NH * NL * NP)  // 128

// Scratch (allocation-free: __device__ globals)
__device__ float g_val [M_ROWS * D_MODEL];   // value @ W_val + b_val
__device__ float g_off [M_ROWS * D_MODEL];   // query @ W_off + b_off
__device__ float g_attn[M_ROWS * NATTN];     // query @ W_attn + b_attn (logits)
__device__ float g_acc [M_ROWS * D_MODEL];   // sampled+weighted accum

__constant__ int c_start[NL] = {0, 10000, 12500, 13125};
__constant__ int c_H[NL]     = {100, 50, 25, 13};
__constant__ int c_W[NL]     = {100, 50, 25, 13};

// ---------------------------------------------------------------------------
// SGEMM: C[M,N] = A[M,256] * B[256,N] + bias[N]
// BM=128, BN=128, BK=8, TM=TN=8, 256 threads. K fixed = 256.
// N must be a multiple of 128; only M has an edge.
// ---------------------------------------------------------------------------
__global__ __launch_bounds__(256, 2)
void sgemm_bias(const float* __restrict__ A, const float* __restrict__ B,
                const float* __restrict__ bias, float* __restrict__ C,
                int M, int N) {
    const int K = 256;
    __shared__ float As[8][128];
    __shared__ float Bs[8][132];  // pad to dodge some bank conflicts

    int tid = threadIdx.x;
    int tx = tid % 16;      // col group
    int ty = tid / 16;      // row group
    int rowBase = blockIdx.y * 128;
    int colBase = blockIdx.x * 128;

    int aRow = tid >> 1;            // 0..127
    int aCol = (tid & 1) * 4;       // 0 or 4
    int bRow = tid >> 5;            // 0..7
    int bCol = (tid & 31) * 4;      // 0..124

    float acc[8][8];
#pragma unroll
    for (int i = 0; i < 8; i++)
#pragma unroll
        for (int j = 0; j < 8; j++) acc[i][j] = 0.f;

    for (int k0 = 0; k0 < K; k0 += 8) {
        float4 av = make_float4(0.f, 0.f, 0.f, 0.f);
        int gr = rowBase + aRow;
        if (gr < M)
            av = *reinterpret_cast<const float4*>(&A[(size_t)gr * K + k0 + aCol]);
        As[aCol + 0][aRow] = av.x;
        As[aCol + 1][aRow] = av.y;
        As[aCol + 2][aRow] = av.z;
        As[aCol + 3][aRow] = av.w;

        float4 bv = *reinterpret_cast<const float4*>(
            &B[(size_t)(k0 + bRow) * N + colBase + bCol]);
        Bs[bRow][bCol + 0] = bv.x;
        Bs[bRow][bCol + 1] = bv.y;
        Bs[bRow][bCol + 2] = bv.z;
        Bs[bRow][bCol + 3] = bv.w;
        __syncthreads();

#pragma unroll
        for (int k = 0; k < 8; k++) {
            float ra[8], rb[8];
#pragma unroll
            for (int i = 0; i < 8; i++) ra[i] = As[k][ty * 8 + i];
#pragma unroll
            for (int j = 0; j < 8; j++) rb[j] = Bs[k][tx * 8 + j];
#pragma unroll
            for (int i = 0; i < 8; i++)
#pragma unroll
                for (int j = 0; j < 8; j++) acc[i][j] += ra[i] * rb[j];
        }
        __syncthreads();
    }

#pragma unroll
    for (int i = 0; i < 8; i++) {
        int r = rowBase + ty * 8 + i;
        if (r >= M) continue;
#pragma unroll
        for (int j = 0; j < 8; j += 4) {
            int cc = colBase + tx * 8 + j;
            float4 o;
            o.x = acc[i][j + 0] + bias[cc + 0];
            o.y = acc[i][j + 1] + bias[cc + 1];
            o.z = acc[i][j + 2] + bias[cc + 2];
            o.w = acc[i][j + 3] + bias[cc + 3];
            *reinterpret_cast<float4*>(&C[(size_t)r * N + cc]) = o;
        }
    }
}

// ---------------------------------------------------------------------------
// Sampler: one block per (b, q). 256 threads.
// Phase 1: threads 0..127 (one per (h,l,p) combo) compute the 4 bilinear
//          corner indices + weights; logits staged for softmax.
// Phase 2: threads 0..7 (one per head) do the 16-way softmax.
// Phase 3: combo threads fold softmax weight into corner weights.
// Phase 4: thread (h,d) accumulates 16 combos x 4 corners of val, coalesced
//          across d within each warp.
// ---------------------------------------------------------------------------
__global__ __launch_bounds__(256, 4)
void sampler(const float* __restrict__ refp,
             const float* __restrict__ offs,
             const float* __restrict__ attn,
             const float* __restrict__ val,
             float* __restrict__ out_acc) {
    int bq = blockIdx.x;       // 0..M_ROWS-1
    int b  = bq / LQ;
    int t  = threadIdx.x;

    __shared__ int   s_idx[NATTN * 4];
    __shared__ float s_w  [NATTN * 4];
    __shared__ float s_sm [NATTN];

    if (t < NATTN) {
        int l = (t >> 2) & 3;
        float lw = (float)c_W[l];
        float lh = (float)c_H[l];
        int   Wl = c_W[l], Hl = c_H[l], st = c_start[l];

        float rx = refp[((size_t)bq * NL + l) * 2 + 0];
        float ry = refp[((size_t)bq * NL + l) * 2 + 1];
        float ox = offs[(size_t)bq * D_MODEL + t * 2 + 0];
        float oy = offs[(size_t)bq * D_MODEL + t * 2 + 1];

        float x = (rx + ox / lw) * lw - 0.5f;
        float y = (ry + oy / lh) * lh - 0.5f;
        float x0f = floorf(x), y0f = floorf(y);
        float wx1 = x - x0f, wx0 = 1.f - wx1;
        float wy1 = y - y0f, wy0 = 1.f - wy1;
        int ix0 = (int)x0f, iy0 = (int)y0f;
        int ix1 = ix0 + 1,  iy1 = iy0 + 1;

        bool inx0 = (ix0 >= 0) && (ix0 <= Wl - 1);
        bool inx1 = (ix1 >= 0) && (ix1 <= Wl - 1);
        bool iny0 = (iy0 >= 0) && (iy0 <= Hl - 1);
        bool iny1 = (iy1 >= 0) && (iy1 <= Hl - 1);
        int cx0 = min(max(ix0, 0), Wl - 1);
        int cx1 = min(max(ix1, 0), Wl - 1);
        int cy0 = min(max(iy0, 0), Hl - 1);
        int cy1 = min(max(iy1, 0), Hl - 1);

        s_idx[t * 4 + 0] = st + cy0 * Wl + cx0;
        s_idx[t * 4 + 1] = st + cy0 * Wl + cx1;
        s_idx[t * 4 + 2] = st + cy1 * Wl + cx0;
        s_idx[t * 4 + 3] = st + cy1 * Wl + cx1;
        s_w[t * 4 + 0] = (inx0 && iny0) ? wx0 * wy0 : 0.f;
        s_w[t * 4 + 1] = (inx1 && iny0) ? wx1 * wy0 : 0.f;
        s_w[t * 4 + 2] = (inx0 && iny1) ? wx0 * wy1 : 0.f;
        s_w[t * 4 + 3] = (inx1 && iny1) ? wx1 * wy1 : 0.f;

        s_sm[t] = attn[(size_t)bq * NATTN + t];
    }
    __syncthreads();

    if (t < NH) {
        float m = -1e30f;
#pragma unroll
        for (int j = 0; j < 16; j++) m = fmaxf(m, s_sm[t * 16 + j]);
        float e[16], sum = 0.f;
#pragma unroll
        for (int j = 0; j < 16; j++) { e[j] = expf(s_sm[t * 16 + j] - m); sum += e[j]; }
        float inv = 1.f / sum;
#pragma unroll
        for (int j = 0; j < 16; j++) s_sm[t * 16 + j] = e[j] * inv;
    }
    __syncthreads();

    if (t < NATTN) {
        float sw = s_sm[t];
        s_w[t * 4 + 0] *= sw;
        s_w[t * 4 + 1] *= sw;
        s_w[t * 4 + 2] *= sw;
        s_w[t * 4 + 3] *= sw;
    }
    __syncthreads();

    int h = t >> 5;
    int d = t & 31;
    const float* vb = val + (size_t)b * S_TOT * D_MODEL + h * HD + d;
    float acc = 0.f;
    int base = h * 64;  // 16 combos * 4 corners
#pragma unroll
    for (int j = 0; j < 64; j++) {
        float w = s_w[base + j];
        int   s = s_idx[base + j];
        acc += w * __ldg(vb + (size_t)s * D_MODEL);
    }
    out_acc[(size_t)bq * D_MODEL + t] = acc;
}

// ---------------------------------------------------------------------------
extern "C" void kernel_launch(void* const* d_in, const int* in_sizes, int n_in,
                              void* d_out, int out_size) {
    const float* query  = (const float*)d_in[0];
    const float* refp   = (const float*)d_in[1];
    const float* value  = (const float*)d_in[2];
    const float* W_val  = (const float*)d_in[3];
    const float* b_val  = (const float*)d_in[4];
    const float* W_off  = (const float*)d_in[5];
    const float* b_off  = (const float*)d_in[6];
    const float* W_attn = (const float*)d_in[7];
    const float* b_attn = (const float*)d_in[8];
    const float* W_out  = (const float*)d_in[9];
    const float* b_out  = (const float*)d_in[10];
    float* out = (float*)d_out;

    float *pval, *poff, *pattn, *pacc;
    cudaGetSymbolAddress((void**)&pval,  g_val);
    cudaGetSymbolAddress((void**)&poff,  g_off);
    cudaGetSymbolAddress((void**)&pattn, g_attn);
    cudaGetSymbolAddress((void**)&pacc,  g_acc);

    dim3 blk(256);
    int mBlocks = (M_ROWS + 127) / 128;  // 208

    sgemm_bias<<<dim3(2, mBlocks), blk>>>(value, W_val,  b_val,  pval,  M_ROWS, 256);
    sgemm_bias<<<dim3(2, mBlocks), blk>>>(query, W_off,  b_off,  poff,  M_ROWS, 256);
    sgemm_bias<<<dim3(1, mBlocks), blk>>>(query, W_attn, b_attn, pattn, M_ROWS, 128);
    sampler<<<M_ROWS, blk>>>(refp, poff, pattn, pval, pacc);
    sgemm_bias<<<dim3(2, mBlocks), blk>>>(pacc, W_out, b_out, out, M_ROWS, 256);
}

// round 3
// speedup vs baseline: 1.8415x; 1.8415x over previous
#include <cuda_runtime.h>
#include <cstdint>
#include <math.h>

#define D_MODEL 256
#define NH 8
#define NL 4
#define NP 4
#define HD 32
#define BATCH 2
#define S_TOT 13294
#define LQ 13294
#define M_ROWS (BATCH * LQ)   // 26588
#define NATTN (NH * NL * NP)  // 128

// ---------------- scratch (allocation-free) ----------------
__device__ float g_val [M_ROWS * D_MODEL];
__device__ float g_off [M_ROWS * D_MODEL];
__device__ float g_attn[M_ROWS * NATTN];
__device__ float g_acc [M_ROWS * D_MODEL];

__constant__ int c_start[NL] = {0, 10000, 12500, 13125};
__constant__ int c_H[NL]     = {100, 50, 25, 13};
__constant__ int c_W[NL]     = {100, 50, 25, 13};

__device__ __forceinline__ float to_tf32(float x) {
    float y; asm("cvt.rna.tf32.f32 %0, %1;" : "=f"(y) : "f"(x)); return y;
}

// ---------------------------------------------------------------------------
// Tensor-core GEMM via mma.sync.m16n8k8.tf32 (compute_103-safe PTX).
//   C[M,N] = A[M,256] @ W[256,N] + bias[N]
// CTA tile 128x128, BK=32, 256 threads = 8 warps, warp tile 64x32.
// A and W rounded to tf32 (rna) in the load path; fp32 accumulate.
// Double-buffered SMEM; register-staged global prefetch.
// SMEM layout: As[buf][128][36] (pad->banks 4g+t), Bs[buf][32][136] (banks 8t+g).
// ---------------------------------------------------------------------------
#define ASTRIDE 36
#define BSTRIDE 136
#define ASZ (128 * ASTRIDE)   // floats per A buffer
#define BSZ (32 * BSTRIDE)    // floats per B buffer

template <int N>
__global__ void __launch_bounds__(256, 1)
gemm_mma(const float* __restrict__ A, const float* __restrict__ W,
         const float* __restrict__ bias, float* __restrict__ C, int M) {
    extern __shared__ float sm[];
    float* As = sm;                 // 2 * ASZ
    float* Bs = sm + 2 * ASZ;       // 2 * BSZ

    const int tid = threadIdx.x;
    const int wid = tid >> 5, lane = tid & 31;
    const int g = lane >> 2, t = lane & 3;          // mma quad coords
    const int wm = wid & 1;                          // 2 m-warp tiles (64 rows)
    const int wn = wid >> 1;                         // 4 n-warp tiles (32 cols)
    const int rowBase = blockIdx.y * 128;
    const int colBase = blockIdx.x * 128;

    float acc[4][4][4];
#pragma unroll
    for (int i = 0; i < 4; i++)
#pragma unroll
        for (int j = 0; j < 4; j++)
#pragma unroll
            for (int r = 0; r < 4; r++) acc[i][j][r] = 0.f;

    float4 pa[4], pb[4];

    auto ldg_tile = [&](int c) {
        const int c0 = c * 32;
#pragma unroll
        for (int i = 0; i < 4; i++) {
            int e = tid + i * 256;
            int r = e >> 3, f4 = e & 7;
            int row = rowBase + r; if (row >= M) row = M - 1;
            pa[i] = *reinterpret_cast<const float4*>(&A[(size_t)row * 256 + c0 + f4 * 4]);
        }
#pragma unroll
        for (int i = 0; i < 4; i++) {
            int e = tid + i * 256;
            int k = e >> 5, f4 = e & 31;
            pb[i] = *reinterpret_cast<const float4*>(&W[(size_t)(c0 + k) * N + colBase + f4 * 4]);
        }
    };
    auto sts_tile = [&](int p) {
        float* Ab = As + p * ASZ;
        float* Bb = Bs + p * BSZ;
#pragma unroll
        for (int i = 0; i < 4; i++) {
            int e = tid + i * 256;
            int r = e >> 3, f4 = e & 7;
            float4 v = pa[i];
            v.x = to_tf32(v.x); v.y = to_tf32(v.y); v.z = to_tf32(v.z); v.w = to_tf32(v.w);
            *reinterpret_cast<float4*>(&Ab[r * ASTRIDE + f4 * 4]) = v;
        }
#pragma unroll
        for (int i = 0; i < 4; i++) {
            int e = tid + i * 256;
            int k = e >> 5, f4 = e & 31;
            float4 v = pb[i];
            v.x = to_tf32(v.x); v.y = to_tf32(v.y); v.z = to_tf32(v.z); v.w = to_tf32(v.w);
            *reinterpret_cast<float4*>(&Bb[k * BSTRIDE + f4 * 4]) = v;
        }
    };

    ldg_tile(0);
    sts_tile(0);
    __syncthreads();

    for (int c = 0; c < 8; c++) {
        const int p = c & 1;
        if (c < 7) ldg_tile(c + 1);

        const float* Ab = As + p * ASZ;
        const float* Bb = Bs + p * BSZ;
#pragma unroll
        for (int ks = 0; ks < 4; ks++) {
            const int k0 = ks * 8;
            uint32_t af[4][4];
#pragma unroll
            for (int im = 0; im < 4; im++) {
                int m0 = wm * 64 + im * 16;
                const float* ap = &Ab[(m0 + g) * ASTRIDE + k0 + t];
                af[im][0] = __float_as_uint(ap[0]);
                af[im][1] = __float_as_uint(ap[8 * ASTRIDE]);
                af[im][2] = __float_as_uint(ap[4]);
                af[im][3] = __float_as_uint(ap[8 * ASTRIDE + 4]);
            }
            uint32_t bf[4][2];
#pragma unroll
            for (int jn = 0; jn < 4; jn++) {
                int n0 = wn * 32 + jn * 8;
                const float* bp = &Bb[(k0 + t) * BSTRIDE + n0 + g];
                bf[jn][0] = __float_as_uint(bp[0]);
                bf[jn][1] = __float_as_uint(bp[4 * BSTRIDE]);
            }
#pragma unroll
            for (int im = 0; im < 4; im++)
#pragma unroll
                for (int jn = 0; jn < 4; jn++) {
                    asm volatile(
                        "mma.sync.aligned.m16n8k8.row.col.f32.tf32.tf32.f32 "
                        "{%0,%1,%2,%3}, {%4,%5,%6,%7}, {%8,%9}, {%0,%1,%2,%3};"
                        : "+f"(acc[im][jn][0]), "+f"(acc[im][jn][1]),
                          "+f"(acc[im][jn][2]), "+f"(acc[im][jn][3])
                        : "r"(af[im][0]), "r"(af[im][1]), "r"(af[im][2]), "r"(af[im][3]),
                          "r"(bf[jn][0]), "r"(bf[jn][1]));
                }
        }

        if (c < 7) sts_tile(1 - p);
        __syncthreads();
    }

    // Epilogue: direct stores + bias.  c0/c1 -> row g; c2/c3 -> row g+8.
#pragma unroll
    for (int im = 0; im < 4; im++) {
        int row0 = rowBase + wm * 64 + im * 16 + g;
#pragma unroll
        for (int jn = 0; jn < 4; jn++) {
            int col = colBase + wn * 32 + jn * 8 + 2 * t;
            float b0 = bias[col], b1 = bias[col + 1];
            if (row0 < M) {
                float2 v = make_float2(acc[im][jn][0] + b0, acc[im][jn][1] + b1);
                *reinterpret_cast<float2*>(&C[(size_t)row0 * N + col]) = v;
            }
            if (row0 + 8 < M) {
                float2 v = make_float2(acc[im][jn][2] + b0, acc[im][jn][3] + b1);
                *reinterpret_cast<float2*>(&C[(size_t)(row0 + 8) * N + col]) = v;
            }
        }
    }
}

// ---------------------------------------------------------------------------
// Sampler (unchanged): one block per (b,q), 256 threads.
// ---------------------------------------------------------------------------
__global__ __launch_bounds__(256, 4)
void sampler(const float* __restrict__ refp,
             const float* __restrict__ offs,
             const float* __restrict__ attn,
             const float* __restrict__ val,
             float* __restrict__ out_acc) {
    int bq = blockIdx.x;
    int b  = bq / LQ;
    int t  = threadIdx.x;

    __shared__ int   s_idx[NATTN * 4];
    __shared__ float s_w  [NATTN * 4];
    __shared__ float s_sm [NATTN];

    if (t < NATTN) {
        int l = (t >> 2) & 3;
        float lw = (float)c_W[l];
        float lh = (float)c_H[l];
        int   Wl = c_W[l], Hl = c_H[l], st = c_start[l];

        float rx = refp[((size_t)bq * NL + l) * 2 + 0];
        float ry = refp[((size_t)bq * NL + l) * 2 + 1];
        float ox = offs[(size_t)bq * D_MODEL + t * 2 + 0];
        float oy = offs[(size_t)bq * D_MODEL + t * 2 + 1];

        float x = (rx + ox / lw) * lw - 0.5f;
        float y = (ry + oy / lh) * lh - 0.5f;
        float x0f = floorf(x), y0f = floorf(y);
        float wx1 = x - x0f, wx0 = 1.f - wx1;
        float wy1 = y - y0f, wy0 = 1.f - wy1;
        int ix0 = (int)x0f, iy0 = (int)y0f;
        int ix1 = ix0 + 1,  iy1 = iy0 + 1;

        bool inx0 = (ix0 >= 0) && (ix0 <= Wl - 1);
        bool inx1 = (ix1 >= 0) && (ix1 <= Wl - 1);
        bool iny0 = (iy0 >= 0) && (iy0 <= Hl - 1);
        bool iny1 = (iy1 >= 0) && (iy1 <= Hl - 1);
        int cx0 = min(max(ix0, 0), Wl - 1);
        int cx1 = min(max(ix1, 0), Wl - 1);
        int cy0 = min(max(iy0, 0), Hl - 1);
        int cy1 = min(max(iy1, 0), Hl - 1);

        s_idx[t * 4 + 0] = st + cy0 * Wl + cx0;
        s_idx[t * 4 + 1] = st + cy0 * Wl + cx1;
        s_idx[t * 4 + 2] = st + cy1 * Wl + cx0;
        s_idx[t * 4 + 3] = st + cy1 * Wl + cx1;
        s_w[t * 4 + 0] = (inx0 && iny0) ? wx0 * wy0 : 0.f;
        s_w[t * 4 + 1] = (inx1 && iny0) ? wx1 * wy0 : 0.f;
        s_w[t * 4 + 2] = (inx0 && iny1) ? wx0 * wy1 : 0.f;
        s_w[t * 4 + 3] = (inx1 && iny1) ? wx1 * wy1 : 0.f;

        s_sm[t] = attn[(size_t)bq * NATTN + t];
    }
    __syncthreads();

    if (t < NH) {
        float m = -1e30f;
#pragma unroll
        for (int j = 0; j < 16; j++) m = fmaxf(m, s_sm[t * 16 + j]);
        float e[16], sum = 0.f;
#pragma unroll
        for (int j = 0; j < 16; j++) { e[j] = expf(s_sm[t * 16 + j] - m); sum += e[j]; }
        float inv = 1.f / sum;
#pragma unroll
        for (int j = 0; j < 16; j++) s_sm[t * 16 + j] = e[j] * inv;
    }
    __syncthreads();

    if (t < NATTN) {
        float sw = s_sm[t];
        s_w[t * 4 + 0] *= sw;
        s_w[t * 4 + 1] *= sw;
        s_w[t * 4 + 2] *= sw;
        s_w[t * 4 + 3] *= sw;
    }
    __syncthreads();

    int h = t >> 5;
    int d = t & 31;
    const float* vb = val + (size_t)b * S_TOT * D_MODEL + h * HD + d;
    float acc = 0.f;
    int base = h * 64;
#pragma unroll
    for (int j = 0; j < 64; j++) {
        float w = s_w[base + j];
        int   s = s_idx[base + j];
        acc += w * __ldg(vb + (size_t)s * D_MODEL);
    }
    out_acc[(size_t)bq * D_MODEL + t] = acc;
}

// ---------------------------------------------------------------------------
extern "C" void kernel_launch(void* const* d_in, const int* in_sizes, int n_in,
                              void* d_out, int out_size) {
    const float* query  = (const float*)d_in[0];
    const float* refp   = (const float*)d_in[1];
    const float* value  = (const float*)d_in[2];
    const float* W_val  = (const float*)d_in[3];
    const float* b_val  = (const float*)d_in[4];
    const float* W_off  = (const float*)d_in[5];
    const float* b_off  = (const float*)d_in[6];
    const float* W_attn = (const float*)d_in[7];
    const float* b_attn = (const float*)d_in[8];
    const float* W_out  = (const float*)d_in[9];
    const float* b_out  = (const float*)d_in[10];
    float* out = (float*)d_out;

    float *pval, *poff, *pattn, *pacc;
    cudaGetSymbolAddress((void**)&pval,  g_val);
    cudaGetSymbolAddress((void**)&poff,  g_off);
    cudaGetSymbolAddress((void**)&pattn, g_attn);
    cudaGetSymbolAddress((void**)&pacc,  g_acc);

    const int SMEM = (2 * ASZ + 2 * BSZ) * 4;   // 71680 B
    static bool configured = false;
    if (!configured) {
        cudaFuncSetAttribute((const void*)gemm_mma<256>,
                             cudaFuncAttributeMaxDynamicSharedMemorySize, SMEM);
        cudaFuncSetAttribute((const void*)gemm_mma<128>,
                             cudaFuncAttributeMaxDynamicSharedMemorySize, SMEM);
        configured = true;
    }

    int mBlocks = (M_ROWS + 127) / 128;   // 208

    gemm_mma<256><<<dim3(2, mBlocks), 256, SMEM>>>(value, W_val,  b_val,  pval,  M_ROWS);
    gemm_mma<256><<<dim3(2, mBlocks), 256, SMEM>>>(query, W_off,  b_off,  poff,  M_ROWS);
    gemm_mma<128><<<dim3(1, mBlocks), 256, SMEM>>>(query, W_attn, b_attn, pattn, M_ROWS);

    sampler<<<M_ROWS, 256>>>(refp, poff, pattn, pval, pacc);

    gemm_mma<256><<<dim3(2, mBlocks), 256, SMEM>>>(pacc, W_out, b_out, out, M_ROWS);
}

// round 4
// speedup vs baseline: 1.8442x; 1.0015x over previous
#include <cuda_runtime.h>
#include <cstdint>
#include <math.h>

#define D_MODEL 256
#define NH 8
#define NL 4
#define NP 4
#define HD 32
#define BATCH 2
#define S_TOT 13294
#define LQ 13294
#define M_ROWS (BATCH * LQ)   // 26588
#define NATTN (NH * NL * NP)  // 128
#define NCAT 384              // 256 (off) + 128 (attn)

// ---------------- scratch (allocation-free) ----------------
__device__ float g_val    [M_ROWS * D_MODEL];
__device__ float g_offattn[M_ROWS * NCAT];
__device__ float g_acc    [M_ROWS * D_MODEL];
__device__ float g_Wcat   [D_MODEL * NCAT];
__device__ float g_bcat   [NCAT];

__constant__ int c_start[NL] = {0, 10000, 12500, 13125};
__constant__ int c_H[NL]     = {100, 50, 25, 13};
__constant__ int c_W[NL]     = {100, 50, 25, 13};

__device__ __forceinline__ float to_tf32(float x) {
    float y; asm("cvt.rna.tf32.f32 %0, %1;" : "=f"(y) : "f"(x)); return y;
}

// ---------------------------------------------------------------------------
// concat [W_off | W_attn] -> g_Wcat[256][384], biases -> g_bcat[384]
// ---------------------------------------------------------------------------
__global__ void concat_wb(const float* __restrict__ W_off, const float* __restrict__ b_off,
                          const float* __restrict__ W_attn, const float* __restrict__ b_attn,
                          float* __restrict__ Wcat, float* __restrict__ bcat) {
    int k = blockIdx.x;          // 0..255
    int n = threadIdx.x;         // 0..383
    float v = (n < 256) ? W_off[k * 256 + n] : W_attn[k * 128 + (n - 256)];
    Wcat[k * NCAT + n] = v;
    if (k == 0) bcat[n] = (n < 256) ? b_off[n] : b_attn[n - 256];
}

// ---------------------------------------------------------------------------
// Tensor-core GEMM via mma.sync.m16n8k8.tf32:
//   C[M,N] = A[M,256] @ W[256,N] + bias[N]
// CTA tile 128x128, BK=32, 8 warps (warp tile 64x32), double-buffered SMEM.
// ---------------------------------------------------------------------------
#define ASTRIDE 36
#define BSTRIDE 136
#define ASZ (128 * ASTRIDE)
#define BSZ (32 * BSTRIDE)

template <int N>
__global__ void __launch_bounds__(256, 1)
gemm_mma(const float* __restrict__ A, const float* __restrict__ W,
         const float* __restrict__ bias, float* __restrict__ C, int M) {
    extern __shared__ float sm[];
    float* As = sm;
    float* Bs = sm + 2 * ASZ;

    const int tid = threadIdx.x;
    const int wid = tid >> 5, lane = tid & 31;
    const int g = lane >> 2, t = lane & 3;
    const int wm = wid & 1;
    const int wn = wid >> 1;
    const int rowBase = blockIdx.y * 128;
    const int colBase = blockIdx.x * 128;

    float acc[4][4][4];
#pragma unroll
    for (int i = 0; i < 4; i++)
#pragma unroll
        for (int j = 0; j < 4; j++)
#pragma unroll
            for (int r = 0; r < 4; r++) acc[i][j][r] = 0.f;

    float4 pa[4], pb[4];

    auto ldg_tile = [&](int c) {
        const int c0 = c * 32;
#pragma unroll
        for (int i = 0; i < 4; i++) {
            int e = tid + i * 256;
            int r = e >> 3, f4 = e & 7;
            int row = rowBase + r; if (row >= M) row = M - 1;
            pa[i] = *reinterpret_cast<const float4*>(&A[(size_t)row * 256 + c0 + f4 * 4]);
        }
#pragma unroll
        for (int i = 0; i < 4; i++) {
            int e = tid + i * 256;
            int k = e >> 5, f4 = e & 31;
            pb[i] = *reinterpret_cast<const float4*>(&W[(size_t)(c0 + k) * N + colBase + f4 * 4]);
        }
    };
    auto sts_tile = [&](int p) {
        float* Ab = As + p * ASZ;
        float* Bb = Bs + p * BSZ;
#pragma unroll
        for (int i = 0; i < 4; i++) {
            int e = tid + i * 256;
            int r = e >> 3, f4 = e & 7;
            float4 v = pa[i];
            v.x = to_tf32(v.x); v.y = to_tf32(v.y); v.z = to_tf32(v.z); v.w = to_tf32(v.w);
            *reinterpret_cast<float4*>(&Ab[r * ASTRIDE + f4 * 4]) = v;
        }
#pragma unroll
        for (int i = 0; i < 4; i++) {
            int e = tid + i * 256;
            int k = e >> 5, f4 = e & 31;
            float4 v = pb[i];
            v.x = to_tf32(v.x); v.y = to_tf32(v.y); v.z = to_tf32(v.z); v.w = to_tf32(v.w);
            *reinterpret_cast<float4*>(&Bb[k * BSTRIDE + f4 * 4]) = v;
        }
    };

    ldg_tile(0);
    sts_tile(0);
    __syncthreads();

    for (int c = 0; c < 8; c++) {
        const int p = c & 1;
        if (c < 7) ldg_tile(c + 1);

        const float* Ab = As + p * ASZ;
        const float* Bb = Bs + p * BSZ;
#pragma unroll
        for (int ks = 0; ks < 4; ks++) {
            const int k0 = ks * 8;
            uint32_t af[4][4];
#pragma unroll
            for (int im = 0; im < 4; im++) {
                int m0 = wm * 64 + im * 16;
                const float* ap = &Ab[(m0 + g) * ASTRIDE + k0 + t];
                af[im][0] = __float_as_uint(ap[0]);
                af[im][1] = __float_as_uint(ap[8 * ASTRIDE]);
                af[im][2] = __float_as_uint(ap[4]);
                af[im][3] = __float_as_uint(ap[8 * ASTRIDE + 4]);
            }
            uint32_t bf[4][2];
#pragma unroll
            for (int jn = 0; jn < 4; jn++) {
                int n0 = wn * 32 + jn * 8;
                const float* bp = &Bb[(k0 + t) * BSTRIDE + n0 + g];
                bf[jn][0] = __float_as_uint(bp[0]);
                bf[jn][1] = __float_as_uint(bp[4 * BSTRIDE]);
            }
#pragma unroll
            for (int im = 0; im < 4; im++)
#pragma unroll
                for (int jn = 0; jn < 4; jn++) {
                    asm volatile(
                        "mma.sync.aligned.m16n8k8.row.col.f32.tf32.tf32.f32 "
                        "{%0,%1,%2,%3}, {%4,%5,%6,%7}, {%8,%9}, {%0,%1,%2,%3};"
                        : "+f"(acc[im][jn][0]), "+f"(acc[im][jn][1]),
                          "+f"(acc[im][jn][2]), "+f"(acc[im][jn][3])
                        : "r"(af[im][0]), "r"(af[im][1]), "r"(af[im][2]), "r"(af[im][3]),
                          "r"(bf[jn][0]), "r"(bf[jn][1]));
                }
        }

        if (c < 7) sts_tile(1 - p);
        __syncthreads();
    }

#pragma unroll
    for (int im = 0; im < 4; im++) {
        int row0 = rowBase + wm * 64 + im * 16 + g;
#pragma unroll
        for (int jn = 0; jn < 4; jn++) {
            int col = colBase + wn * 32 + jn * 8 + 2 * t;
            float b0 = bias[col], b1 = bias[col + 1];
            if (row0 < M) {
                float2 v = make_float2(acc[im][jn][0] + b0, acc[im][jn][1] + b1);
                *reinterpret_cast<float2*>(&C[(size_t)row0 * N + col]) = v;
            }
            if (row0 + 8 < M) {
                float2 v = make_float2(acc[im][jn][2] + b0, acc[im][jn][3] + b1);
                *reinterpret_cast<float2*>(&C[(size_t)(row0 + 8) * N + col]) = v;
            }
        }
    }
}

// ---------------------------------------------------------------------------
// Sampler: one block per (b,q), 256 threads.
// Phase 1: 128 threads -> corner idx/weight, packed (w, idx) float2 in SMEM.
// Phase 2: 8 threads -> per-head 16-way softmax.
// Phase 3: fold softmax into packed weights.
// Phase 4: warp = head; lane = (sub 0..3, d4 0..7); float4 gathers, 2 accs,
//          shuffle-reduce over sub, float4 store.
// ---------------------------------------------------------------------------
__global__ __launch_bounds__(256, 4)
void sampler(const float* __restrict__ refp,
             const float* __restrict__ offattn,
             const float* __restrict__ val,
             float* __restrict__ out_acc) {
    int bq = blockIdx.x;
    int b  = bq / LQ;
    int t  = threadIdx.x;

    __shared__ float2 s_pack[NATTN * 4];   // (weight, idx bits)
    __shared__ float  s_sm  [NATTN];

    if (t < NATTN) {
        int l = (t >> 2) & 3;
        float lw = (float)c_W[l];
        float lh = (float)c_H[l];
        int   Wl = c_W[l], Hl = c_H[l], st = c_start[l];

        float rx = refp[((size_t)bq * NL + l) * 2 + 0];
        float ry = refp[((size_t)bq * NL + l) * 2 + 1];
        float ox = offattn[(size_t)bq * NCAT + t * 2 + 0];
        float oy = offattn[(size_t)bq * NCAT + t * 2 + 1];

        float x = (rx + ox / lw) * lw - 0.5f;
        float y = (ry + oy / lh) * lh - 0.5f;
        float x0f = floorf(x), y0f = floorf(y);
        float wx1 = x - x0f, wx0 = 1.f - wx1;
        float wy1 = y - y0f, wy0 = 1.f - wy1;
        int ix0 = (int)x0f, iy0 = (int)y0f;
        int ix1 = ix0 + 1,  iy1 = iy0 + 1;

        bool inx0 = (ix0 >= 0) && (ix0 <= Wl - 1);
        bool inx1 = (ix1 >= 0) && (ix1 <= Wl - 1);
        bool iny0 = (iy0 >= 0) && (iy0 <= Hl - 1);
        bool iny1 = (iy1 >= 0) && (iy1 <= Hl - 1);
        int cx0 = min(max(ix0, 0), Wl - 1);
        int cx1 = min(max(ix1, 0), Wl - 1);
        int cy0 = min(max(iy0, 0), Hl - 1);
        int cy1 = min(max(iy1, 0), Hl - 1);

        s_pack[t * 4 + 0] = make_float2((inx0 && iny0) ? wx0 * wy0 : 0.f,
                                        __int_as_float(st + cy0 * Wl + cx0));
        s_pack[t * 4 + 1] = make_float2((inx1 && iny0) ? wx1 * wy0 : 0.f,
                                        __int_as_float(st + cy0 * Wl + cx1));
        s_pack[t * 4 + 2] = make_float2((inx0 && iny1) ? wx0 * wy1 : 0.f,
                                        __int_as_float(st + cy1 * Wl + cx0));
        s_pack[t * 4 + 3] = make_float2((inx1 && iny1) ? wx1 * wy1 : 0.f,
                                        __int_as_float(st + cy1 * Wl + cx1));

        s_sm[t] = offattn[(size_t)bq * NCAT + 256 + t];
    }
    __syncthreads();

    if (t < NH) {
        float m = -1e30f;
#pragma unroll
        for (int j = 0; j < 16; j++) m = fmaxf(m, s_sm[t * 16 + j]);
        float e[16], sum = 0.f;
#pragma unroll
        for (int j = 0; j < 16; j++) { e[j] = expf(s_sm[t * 16 + j] - m); sum += e[j]; }
        float inv = 1.f / sum;
#pragma unroll
        for (int j = 0; j < 16; j++) s_sm[t * 16 + j] = e[j] * inv;
    }
    __syncthreads();

    if (t < NATTN) {
        float sw = s_sm[t];
        s_pack[t * 4 + 0].x *= sw;
        s_pack[t * 4 + 1].x *= sw;
        s_pack[t * 4 + 2].x *= sw;
        s_pack[t * 4 + 3].x *= sw;
    }
    __syncthreads();

    // Phase 4
    int h    = t >> 5;
    int lane = t & 31;
    int sub  = lane >> 3;
    int d4   = lane & 7;
    const float4* vb4 = reinterpret_cast<const float4*>(
        val + (size_t)b * S_TOT * D_MODEL + h * HD) + d4;

    float4 a0 = make_float4(0.f, 0.f, 0.f, 0.f);
    float4 a1 = make_float4(0.f, 0.f, 0.f, 0.f);
    int base = h * 64 + sub * 16;
#pragma unroll
    for (int i = 0; i < 16; i += 2) {
        float2 p0 = s_pack[base + i];
        float2 p1 = s_pack[base + i + 1];
        int i0 = __float_as_int(p0.y);
        int i1 = __float_as_int(p1.y);
        float4 v0 = __ldg(vb4 + i0 * 64);
        float4 v1 = __ldg(vb4 + i1 * 64);
        a0.x += p0.x * v0.x; a0.y += p0.x * v0.y; a0.z += p0.x * v0.z; a0.w += p0.x * v0.w;
        a1.x += p1.x * v1.x; a1.y += p1.x * v1.y; a1.z += p1.x * v1.z; a1.w += p1.x * v1.w;
    }
    a0.x += a1.x; a0.y += a1.y; a0.z += a1.z; a0.w += a1.w;

#pragma unroll
    for (int off = 16; off >= 8; off >>= 1) {
        a0.x += __shfl_down_sync(0xffffffffu, a0.x, off);
        a0.y += __shfl_down_sync(0xffffffffu, a0.y, off);
        a0.z += __shfl_down_sync(0xffffffffu, a0.z, off);
        a0.w += __shfl_down_sync(0xffffffffu, a0.w, off);
    }
    if (sub == 0) {
        reinterpret_cast<float4*>(out_acc)[(size_t)bq * 64 + h * 8 + d4] = a0;
    }
}

// ---------------------------------------------------------------------------
extern "C" void kernel_launch(void* const* d_in, const int* in_sizes, int n_in,
                              void* d_out, int out_size) {
    const float* query  = (const float*)d_in[0];
    const float* refp   = (const float*)d_in[1];
    const float* value  = (const float*)d_in[2];
    const float* W_val  = (const float*)d_in[3];
    const float* b_val  = (const float*)d_in[4];
    const float* W_off  = (const float*)d_in[5];
    const float* b_off  = (const float*)d_in[6];
    const float* W_attn = (const float*)d_in[7];
    const float* b_attn = (const float*)d_in[8];
    const float* W_out  = (const float*)d_in[9];
    const float* b_out  = (const float*)d_in[10];
    float* out = (float*)d_out;

    float *pval, *poffattn, *pacc, *pWcat, *pbcat;
    cudaGetSymbolAddress((void**)&pval,     g_val);
    cudaGetSymbolAddress((void**)&poffattn, g_offattn);
    cudaGetSymbolAddress((void**)&pacc,     g_acc);
    cudaGetSymbolAddress((void**)&pWcat,    g_Wcat);
    cudaGetSymbolAddress((void**)&pbcat,    g_bcat);

    const int SMEM = (2 * ASZ + 2 * BSZ) * 4;   // 71680 B
    static bool configured = false;
    if (!configured) {
        cudaFuncSetAttribute((const void*)gemm_mma<256>,
                             cudaFuncAttributeMaxDynamicSharedMemorySize, SMEM);
        cudaFuncSetAttribute((const void*)gemm_mma<384>,
                             cudaFuncAttributeMaxDynamicSharedMemorySize, SMEM);
        configured = true;
    }

    int mBlocks = (M_ROWS + 127) / 128;   // 208

    concat_wb<<<256, NCAT>>>(W_off, b_off, W_attn, b_attn, pWcat, pbcat);

    gemm_mma<256><<<dim3(2, mBlocks), 256, SMEM>>>(value, W_val, b_val, pval, M_ROWS);
    gemm_mma<384><<<dim3(3, mBlocks), 256, SMEM>>>(query, pWcat, pbcat, poffattn, M_ROWS);

    sampler<<<M_ROWS, 256>>>(refp, poffattn, pval, pacc);

    gemm_mma<256><<<dim3(2, mBlocks), 256, SMEM>>>(pacc, W_out, b_out, out, M_ROWS);
}

// round 12
// speedup vs baseline: 2.0414x; 1.1070x over previous
#include <cuda_runtime.h>
#include <cuda_fp16.h>
#include <cstdint>
#include <math.h>

#define D_MODEL 256
#define NH 8
#define NL 4
#define NP 4
#define HD 32
#define BATCH 2
#define S_TOT 13294
#define LQ 13294
#define M_ROWS (BATCH * LQ)   // 26588
#define NATTN (NH * NL * NP)  // 128
#define NCAT 384              // 256 (off) + 128 (attn)

// ---------------- scratch (allocation-free) ----------------
__device__ __half g_valh  [BATCH * NH * S_TOT * HD + 64];  // [b][h][s][d] fp16 (+pad for pair spill)
__device__ float  g_offattn[M_ROWS * NCAT];
__device__ float  g_acc    [M_ROWS * D_MODEL];
__device__ float  g_Wcat   [D_MODEL * NCAT];
__device__ float  g_bcat   [NCAT];

__constant__ int c_start[NL] = {0, 10000, 12500, 13125};
__constant__ int c_H[NL]     = {100, 50, 25, 13};
__constant__ int c_W[NL]     = {100, 50, 25, 13};

__device__ __forceinline__ float to_tf32(float x) {
    float y; asm("cvt.rna.tf32.f32 %0, %1;" : "=f"(y) : "f"(x)); return y;
}

// ---------------------------------------------------------------------------
// concat [W_off | W_attn] -> g_Wcat[256][384], biases -> g_bcat[384]
// ---------------------------------------------------------------------------
__global__ void concat_wb(const float* __restrict__ W_off, const float* __restrict__ b_off,
                          const float* __restrict__ W_attn, const float* __restrict__ b_attn,
                          float* __restrict__ Wcat, float* __restrict__ bcat) {
    int k = blockIdx.x;
    int n = threadIdx.x;
    float v = (n < 256) ? W_off[k * 256 + n] : W_attn[k * 128 + (n - 256)];
    Wcat[k * NCAT + n] = v;
    if (k == 0) bcat[n] = (n < 256) ? b_off[n] : b_attn[n - 256];
}

// ---------------------------------------------------------------------------
// Tensor-core GEMM via mma.sync.m16n8k8.tf32:
//   C[M,N] = A[M,256] @ W[256,N] + bias[N]
// CTA tile 128x128, BK=32, 8 warps, double-buffered SMEM.
// HALF_T: store fp16 to [b][h][s][d] transposed layout (val path).
// ---------------------------------------------------------------------------
#define ASTRIDE 36
#define BSTRIDE 136
#define ASZ (128 * ASTRIDE)
#define BSZ (32 * BSTRIDE)

template <int N, bool HALF_T>
__global__ void __launch_bounds__(256, 1)
gemm_mma(const float* __restrict__ A, const float* __restrict__ W,
         const float* __restrict__ bias, void* __restrict__ Cv, int M) {
    extern __shared__ float sm[];
    float* As = sm;
    float* Bs = sm + 2 * ASZ;

    const int tid = threadIdx.x;
    const int wid = tid >> 5, lane = tid & 31;
    const int g = lane >> 2, t = lane & 3;
    const int wm = wid & 1;
    const int wn = wid >> 1;
    const int rowBase = blockIdx.y * 128;
    const int colBase = blockIdx.x * 128;

    float acc[4][4][4];
#pragma unroll
    for (int i = 0; i < 4; i++)
#pragma unroll
        for (int j = 0; j < 4; j++)
#pragma unroll
            for (int r = 0; r < 4; r++) acc[i][j][r] = 0.f;

    float4 pa[4], pb[4];

    auto ldg_tile = [&](int c) {
        const int c0 = c * 32;
#pragma unroll
        for (int i = 0; i < 4; i++) {
            int e = tid + i * 256;
            int r = e >> 3, f4 = e & 7;
            int row = rowBase + r; if (row >= M) row = M - 1;
            pa[i] = *reinterpret_cast<const float4*>(&A[(size_t)row * 256 + c0 + f4 * 4]);
        }
#pragma unroll
        for (int i = 0; i < 4; i++) {
            int e = tid + i * 256;
            int k = e >> 5, f4 = e & 31;
            pb[i] = *reinterpret_cast<const float4*>(&W[(size_t)(c0 + k) * N + colBase + f4 * 4]);
        }
    };
    auto sts_tile = [&](int p) {
        float* Ab = As + p * ASZ;
        float* Bb = Bs + p * BSZ;
#pragma unroll
        for (int i = 0; i < 4; i++) {
            int e = tid + i * 256;
            int r = e >> 3, f4 = e & 7;
            float4 v = pa[i];
            v.x = to_tf32(v.x); v.y = to_tf32(v.y); v.z = to_tf32(v.z); v.w = to_tf32(v.w);
            *reinterpret_cast<float4*>(&Ab[r * ASTRIDE + f4 * 4]) = v;
        }
#pragma unroll
        for (int i = 0; i < 4; i++) {
            int e = tid + i * 256;
            int k = e >> 5, f4 = e & 31;
            float4 v = pb[i];
            v.x = to_tf32(v.x); v.y = to_tf32(v.y); v.z = to_tf32(v.z); v.w = to_tf32(v.w);
            *reinterpret_cast<float4*>(&Bb[k * BSTRIDE + f4 * 4]) = v;
        }
    };

    ldg_tile(0);
    sts_tile(0);
    __syncthreads();

    for (int c = 0; c < 8; c++) {
        const int p = c & 1;
        if (c < 7) ldg_tile(c + 1);

        const float* Ab = As + p * ASZ;
        const float* Bb = Bs + p * BSZ;
#pragma unroll
        for (int ks = 0; ks < 4; ks++) {
            const int k0 = ks * 8;
            uint32_t af[4][4];
#pragma unroll
            for (int im = 0; im < 4; im++) {
                int m0 = wm * 64 + im * 16;
                const float* ap = &Ab[(m0 + g) * ASTRIDE + k0 + t];
                af[im][0] = __float_as_uint(ap[0]);
                af[im][1] = __float_as_uint(ap[8 * ASTRIDE]);
                af[im][2] = __float_as_uint(ap[4]);
                af[im][3] = __float_as_uint(ap[8 * ASTRIDE + 4]);
            }
            uint32_t bf[4][2];
#pragma unroll
            for (int jn = 0; jn < 4; jn++) {
                int n0 = wn * 32 + jn * 8;
                const float* bp = &Bb[(k0 + t) * BSTRIDE + n0 + g];
                bf[jn][0] = __float_as_uint(bp[0]);
                bf[jn][1] = __float_as_uint(bp[4 * BSTRIDE]);
            }
#pragma unroll
            for (int im = 0; im < 4; im++)
#pragma unroll
                for (int jn = 0; jn < 4; jn++) {
                    asm volatile(
                        "mma.sync.aligned.m16n8k8.row.col.f32.tf32.tf32.f32 "
                        "{%0,%1,%2,%3}, {%4,%5,%6,%7}, {%8,%9}, {%0,%1,%2,%3};"
                        : "+f"(acc[im][jn][0]), "+f"(acc[im][jn][1]),
                          "+f"(acc[im][jn][2]), "+f"(acc[im][jn][3])
                        : "r"(af[im][0]), "r"(af[im][1]), "r"(af[im][2]), "r"(af[im][3]),
                          "r"(bf[jn][0]), "r"(bf[jn][1]));
                }
        }

        if (c < 7) sts_tile(1 - p);
        __syncthreads();
    }

#pragma unroll
    for (int im = 0; im < 4; im++) {
        int row0 = rowBase + wm * 64 + im * 16 + g;
#pragma unroll
        for (int jn = 0; jn < 4; jn++) {
            int col = colBase + wn * 32 + jn * 8 + 2 * t;
            float b0 = bias[col], b1 = bias[col + 1];
            if (HALF_T) {
                __half* C = (__half*)Cv;
                int h = col >> 5, d = col & 31;
#pragma unroll
                for (int rr = 0; rr < 2; rr++) {
                    int row = row0 + rr * 8;
                    if (row < M) {
                        int b = row / S_TOT, s = row % S_TOT;
                        __half2 v = __floats2half2_rn(acc[im][jn][rr * 2 + 0] + b0,
                                                      acc[im][jn][rr * 2 + 1] + b1);
                        *reinterpret_cast<__half2*>(
                            &C[(((size_t)b * NH + h) * S_TOT + s) * HD + d]) = v;
                    }
                }
            } else {
                float* C = (float*)Cv;
                if (row0 < M) {
                    float2 v = make_float2(acc[im][jn][0] + b0, acc[im][jn][1] + b1);
                    *reinterpret_cast<float2*>(&C[(size_t)row0 * N + col]) = v;
                }
                if (row0 + 8 < M) {
                    float2 v = make_float2(acc[im][jn][2] + b0, acc[im][jn][3] + b1);
                    *reinterpret_cast<float2*>(&C[(size_t)(row0 + 8) * N + col]) = v;
                }
            }
        }
    }
}

// ---------------------------------------------------------------------------
// Sampler: warp-autonomous. Block = 256 threads = 8 warps = 8 heads of one
// query. No SMEM, no __syncthreads.
// Lane layout in gather: half16 = lane>>4 selects row-pair (y0/y1),
// c2 = (lane>>3)&1 selects corner (x base / base+1), d4 = lane&7 selects
// 4-channel chunk. One uint2 (4 fp16) per lane; a 16-lane group covers one
// 128B line holding BOTH x-corners of a sample row.
// ---------------------------------------------------------------------------
__global__ __launch_bounds__(256, 6)
void sampler(const float* __restrict__ refp,
             const float* __restrict__ offattn,
             const __half* __restrict__ val,
             float* __restrict__ out_acc) {
    const int bq   = blockIdx.x;
    const int b    = bq / LQ;
    const int t    = threadIdx.x;
    const int h    = t >> 5;
    const int lane = t & 31;
    const int c    = lane & 15;          // combo 0..15 within head (dup in both halves)

    // ---- per-combo pair construction ----
    const int l  = c >> 2;
    const int Wl = c_W[l], Hl = c_H[l], st = c_start[l];
    const float lw = (float)Wl, lh = (float)Hl;

    float2 rp = *reinterpret_cast<const float2*>(&refp[((size_t)bq * NL + l) * 2]);
    float2 of = *reinterpret_cast<const float2*>(&offattn[(size_t)bq * NCAT + (h * 16 + c) * 2]);

    float x = (rp.x + of.x / lw) * lw - 0.5f;
    float y = (rp.y + of.y / lh) * lh - 0.5f;
    float x0f = floorf(x), y0f = floorf(y);
    float wx1 = x - x0f, wx0 = 1.f - wx1;
    float wy1 = y - y0f, wy0 = 1.f - wy1;
    int ix0 = (int)x0f, iy0 = (int)y0f;
    int ix1 = ix0 + 1,  iy1 = iy0 + 1;

    float w0 = (ix0 >= 0 && ix0 < Wl) ? wx0 : 0.f;
    float w1 = (ix1 >= 0 && ix1 < Wl) ? wx1 : 0.f;
    int bx;
    if (ix0 < 0) { bx = 0; w0 = w1; w1 = 0.f; }
    else         { bx = min(ix0, Wl - 1); }

    float wy0e = (iy0 >= 0 && iy0 < Hl) ? wy0 : 0.f;
    float wy1e = (iy1 >= 0 && iy1 < Hl) ? wy1 : 0.f;
    int cy0 = min(max(iy0, 0), Hl - 1);
    int cy1 = min(max(iy1, 0), Hl - 1);

    int s0 = st + cy0 * Wl + bx;
    int s1 = st + cy1 * Wl + bx;

    // ---- softmax over the 16 combos (xor-shuffle within 16-lane groups) ----
    float logit = offattn[(size_t)bq * NCAT + 256 + h * 16 + c];
    float m = logit;
#pragma unroll
    for (int xo = 8; xo >= 1; xo >>= 1) m = fmaxf(m, __shfl_xor_sync(0xffffffffu, m, xo));
    float e = __expf(logit - m);
    float sum = e;
#pragma unroll
    for (int xo = 8; xo >= 1; xo >>= 1) sum += __shfl_xor_sync(0xffffffffu, sum, xo);
    float sw = e / sum;

    float wA0 = w0 * wy0e * sw, wA1 = w1 * wy0e * sw;
    float wB0 = w0 * wy1e * sw, wB1 = w1 * wy1e * sw;

    // ---- gather ----
    const int hf = lane >> 4;            // 0: y0-row pair, 1: y1-row pair
    const int c2 = (lane >> 3) & 1;      // corner within pair
    const int d4 = lane & 7;             // channel chunk
    const __half* ph = val + ((size_t)(b * NH + h)) * S_TOT * HD;

    float a0 = 0.f, a1 = 0.f, a2 = 0.f, a3 = 0.f;
#pragma unroll
    for (int j = 0; j < 16; j++) {
        int   sA = __shfl_sync(0xffffffffu, s0, j);
        int   sB = __shfl_sync(0xffffffffu, s1, j);
        float uA0 = __shfl_sync(0xffffffffu, wA0, j);
        float uA1 = __shfl_sync(0xffffffffu, wA1, j);
        float uB0 = __shfl_sync(0xffffffffu, wB0, j);
        float uB1 = __shfl_sync(0xffffffffu, wB1, j);

        int   s = hf ? sB : sA;
        float w = hf ? (c2 ? uB1 : uB0) : (c2 ? uA1 : uA0);

        uint2 v = __ldg(reinterpret_cast<const uint2*>(ph + (size_t)(s + c2) * HD) + d4);
        float2 f0 = __half22float2(*reinterpret_cast<__half2*>(&v.x));
        float2 f1 = __half22float2(*reinterpret_cast<__half2*>(&v.y));
        a0 = fmaf(w, f0.x, a0);
        a1 = fmaf(w, f0.y, a1);
        a2 = fmaf(w, f1.x, a2);
        a3 = fmaf(w, f1.y, a3);
    }

    // reduce lanes {d4, d4+8, d4+16, d4+24} -> lanes 0..7
#pragma unroll
    for (int off = 16; off >= 8; off >>= 1) {
        a0 += __shfl_down_sync(0xffffffffu, a0, off);
        a1 += __shfl_down_sync(0xffffffffu, a1, off);
        a2 += __shfl_down_sync(0xffffffffu, a2, off);
        a3 += __shfl_down_sync(0xffffffffu, a3, off);
    }
    if (lane < 8) {
        reinterpret_cast<float4*>(out_acc)[(size_t)bq * 64 + h * 8 + d4] =
            make_float4(a0, a1, a2, a3);
    }
}

// ---------------------------------------------------------------------------
extern "C" void kernel_launch(void* const* d_in, const int* in_sizes, int n_in,
                              void* d_out, int out_size) {
    const float* query  = (const float*)d_in[0];
    const float* refp   = (const float*)d_in[1];
    const float* value  = (const float*)d_in[2];
    const float* W_val  = (const float*)d_in[3];
    const float* b_val  = (const float*)d_in[4];
    const float* W_off  = (const float*)d_in[5];
    const float* b_off  = (const float*)d_in[6];
    const float* W_attn = (const float*)d_in[7];
    const float* b_attn = (const float*)d_in[8];
    const float* W_out  = (const float*)d_in[9];
    const float* b_out  = (const float*)d_in[10];
    float* out = (float*)d_out;

    __half* pvalh; float *poffattn, *pacc, *pWcat, *pbcat;
    cudaGetSymbolAddress((void**)&pvalh,    g_valh);
    cudaGetSymbolAddress((void**)&poffattn, g_offattn);
    cudaGetSymbolAddress((void**)&pacc,     g_acc);
    cudaGetSymbolAddress((void**)&pWcat,    g_Wcat);
    cudaGetSymbolAddress((void**)&pbcat,    g_bcat);

    const int SMEM = (2 * ASZ + 2 * BSZ) * 4;   // 71680 B
    static bool configured = false;
    if (!configured) {
        cudaFuncSetAttribute((const void*)gemm_mma<256, true>,
                             cudaFuncAttributeMaxDynamicSharedMemorySize, SMEM);
        cudaFuncSetAttribute((const void*)gemm_mma<256, false>,
                             cudaFuncAttributeMaxDynamicSharedMemorySize, SMEM);
        cudaFuncSetAttribute((const void*)gemm_mma<384, false>,
                             cudaFuncAttributeMaxDynamicSharedMemorySize, SMEM);
        configured = true;
    }

    int mBlocks = (M_ROWS + 127) / 128;   // 208

    concat_wb<<<256, NCAT>>>(W_off, b_off, W_attn, b_attn, pWcat, pbcat);

    gemm_mma<256, true ><<<dim3(2, mBlocks), 256, SMEM>>>(value, W_val, b_val, pvalh, M_ROWS);
    gemm_mma<384, false><<<dim3(3, mBlocks), 256, SMEM>>>(query, pWcat, pbcat, poffattn, M_ROWS);

    sampler<<<M_ROWS, 256>>>(refp, poffattn, pvalh, pacc);

    gemm_mma<256, false><<<dim3(2, mBlocks), 256, SMEM>>>(pacc, W_out, b_out, out, M_ROWS);
}